// round 16
// baseline (speedup 1.0000x reference)
#include <cuda_runtime.h>
#include <cuda_fp16.h>

#define BATCH   512
#define SEQ     176
#define DIN     128
#define NH      8
#define HD      64
#define DMODEL  512
#define NEGV    (-9e15f)
#define M_TOTAL (BATCH * SEQ)          // 90112
#define QSCALE  0.1803368787f           // 0.125 * log2(e)

// ---------------- smem layout (bytes) — identical to R15 ----------------
#define WBUF_STRIDE 68
#define WBUF_BYTES  (64 * WBUF_STRIDE * 4)        // 17408
#define KTHS        180
#define KTH_BYTES   (16 * KTHS * 8)               // 23040
#define VSP_STRIDE  33
#define VSP_BYTES   (SEQ * VSP_STRIDE * 4)        // 23232
#define XS_STRIDE   68
#define XS_BYTES    (SEQ * XS_STRIDE * 4)         // 47872
#define VP2S        76
#define VP2_BYTES   (44 * VP2S * 8)               // 26752 (overlays xs)

#define OFF_WBUF 0
#define OFF_KTH  (OFF_WBUF + WBUF_BYTES)
#define OFF_VSP  (OFF_KTH + KTH_BYTES)
#define OFF_XS   (OFF_VSP + VSP_BYTES)            // 63680 (16B aligned)
#define OFF_VP2  OFF_XS
#define SMEM_TOTAL (OFF_XS + XS_BYTES)            // 111552

// pre-converted fp16 operands (packed half2 k-pair words, smem word order)
static __device__ unsigned g_x16[(size_t)M_TOTAL * 64];      // [m][p]
static __device__ unsigned g_W16[3 * DMODEL * 64];           // [z][n][p]

#define XPART (M_TOTAL * 32)            // vectorized x threads (2 words each)
#define WPART (3 * DMODEL * 64)         // w threads (1 word each)
#define PREP_THREADS (XPART + WPART)

__device__ __forceinline__ unsigned packh2(__half2 h) {
    return *reinterpret_cast<unsigned*>(&h);
}
__device__ __forceinline__ __half geth(unsigned w, int sel) {
    __half2 h = *reinterpret_cast<__half2*>(&w);
    return sel ? __high2half(h) : __low2half(h);
}
__device__ __forceinline__ float ex2f(float x) {
    float r; asm("ex2.approx.f32 %0, %1;" : "=f"(r) : "f"(x)); return r;
}

__device__ __forceinline__ void mma_f16(float c[4],
                                        unsigned a0, unsigned a1, unsigned a2, unsigned a3,
                                        unsigned b0, unsigned b1) {
    asm volatile(
        "mma.sync.aligned.m16n8k16.row.col.f32.f16.f16.f32 "
        "{%0,%1,%2,%3}, {%4,%5,%6,%7}, {%8,%9}, {%0,%1,%2,%3};"
        : "+f"(c[0]), "+f"(c[1]), "+f"(c[2]), "+f"(c[3])
        : "r"(a0), "r"(a1), "r"(a2), "r"(a3), "r"(b0), "r"(b1));
}

// ---------------------------------------------------------------------------
// Merged prep kernel: x part vectorized (float4 -> uint2), W part scalar.
// ---------------------------------------------------------------------------
__global__ void prep_kernel(const float* __restrict__ x,
                            const float* __restrict__ Wq,
                            const float* __restrict__ Wk,
                            const float* __restrict__ Wv)
{
    const int idx = blockIdx.x * 256 + threadIdx.x;
    if (idx < XPART) {
        const int m = idx >> 5, p2 = idx & 31;       // p2 = pair-of-words index
        float4 v = *(const float4*)(x + (size_t)m * DIN + 4 * p2);
        uint2 o;
        o.x = packh2(__floats2half2_rn(v.x, v.y));
        o.y = packh2(__floats2half2_rn(v.z, v.w));
        *(uint2*)(g_x16 + (size_t)m * 64 + 2 * p2) = o;
    } else if (idx < PREP_THREADS) {
        const int r = idx - XPART;                    // [z][n][p] flat, 3*512*64
        const int z = r >> 15;
        const int rr = r & 32767;
        const int p = rr >> 9, n = rr & 511;
        const float* W = (z == 0) ? Wq : (z == 1) ? Wk : Wv;
        const float w0 = W[(size_t)(2 * p    ) * DMODEL + n];
        const float w1 = W[(size_t)(2 * p + 1) * DMODEL + n];
        g_W16[z * (DMODEL * 64) + n * 64 + p] = packh2(__floats2half2_rn(w0, w1));
    }
}

// ---------------------------------------------------------------------------
// Fused kernel (R15 + in-register W prefetch). One block per (b,h).
// 352 threads (11 warps), 2 CTAs/SM.
// ---------------------------------------------------------------------------
__global__ void __launch_bounds__(352, 2)
fused_attn_kernel(const float* __restrict__ bq,
                  const float* __restrict__ bk,
                  const float* __restrict__ bv,
                  float* __restrict__ out)
{
    extern __shared__ char sm[];
    unsigned* Wbuf = (unsigned*)(sm + OFF_WBUF);   // [64 n][68]
    uint2*    KTh  = (uint2*)(sm + OFF_KTH);       // [16][180]
    unsigned* KThw = (unsigned*)(sm + OFF_KTH);
    unsigned* Vsp  = (unsigned*)(sm + OFF_VSP);    // [176][33]
    unsigned* xs   = (unsigned*)(sm + OFF_XS);     // [176][68]
    uint2*    Vp2  = (uint2*)(sm + OFF_VP2);       // [44][76]

    const int tid = threadIdx.x;
    const int bh  = blockIdx.x;
    const int b   = bh >> 3;
    const int h   = bh & 7;
    const int n0  = h * HD;

    // ---- stage x[b]: pure uint4 copy ----
    const unsigned* xg = g_x16 + (size_t)b * SEQ * 64;
    for (int i = tid; i < SEQ * 16; i += 352) {
        const int r = i >> 4, c = (i & 15) * 4;
        *(uint4*)(xs + r * XS_STRIDE + c) = *(const uint4*)(xg + r * 64 + c);
    }

    // ---- stage W for pass z=0 (V) ----
    {
        const unsigned* wg = g_W16 + 2 * (DMODEL * 64) + (size_t)n0 * 64;  // z-order 2 = Wv
        for (int i = tid; i < 64 * 16; i += 352) {
            const int n = i >> 4, c = (i & 15) * 4;
            *(uint4*)(Wbuf + n * WBUF_STRIDE + c) = *(const uint4*)(wg + n * 64 + c);
        }
    }
    __syncthreads();

    const int w    = tid >> 5;
    const int lane = tid & 31;
    const int gid  = lane >> 2;
    const int tig  = lane & 3;
    const int row0 = w * 16 + gid;
    const int row1 = row0 + 8;
    const int lo0  = (row0 / 22) * 22;
    const int lo1  = (row1 / 22) * 22;

    unsigned qa[4][4];   // Q score A-fragments (filled by z==2 pass)

    // per-thread staging map for W prefetch (3 uint4 per thread)
    // i = tid + j*352, i < 1024 : n = i>>4, c = (i&15)*4
    // ---- Phase 1: three projection passes (V, K, Q) ----
    #pragma unroll 1
    for (int z = 0; z < 3; z++) {
        const float* bb = (z == 0) ? bv : (z == 1) ? bk : bq;

        // prefetch next W tile into registers (overlaps the mma loop below)
        uint4 wpre[3];
        if (z < 2) {
            const int wzn = (z == 0) ? 1 : 0;   // next: K then Q
            const unsigned* wgn = g_W16 + wzn * (DMODEL * 64) + (size_t)n0 * 64;
            #pragma unroll
            for (int j = 0; j < 3; j++) {
                const int i = tid + j * 352;
                if (i < 1024) {
                    const int n = i >> 4, c = (i & 15) * 4;
                    wpre[j] = __ldg((const uint4*)(wgn + n * 64 + c));
                }
            }
        }

        float acc[8][4];
        #pragma unroll
        for (int nt = 0; nt < 8; nt++)
            #pragma unroll
            for (int i = 0; i < 4; i++) acc[nt][i] = 0.f;

        #pragma unroll
        for (int ks = 0; ks < 8; ks++) {
            const unsigned a0 = xs[row0 * XS_STRIDE + 8 * ks + tig];
            const unsigned a1 = xs[row1 * XS_STRIDE + 8 * ks + tig];
            const unsigned a2 = xs[row0 * XS_STRIDE + 8 * ks + tig + 4];
            const unsigned a3 = xs[row1 * XS_STRIDE + 8 * ks + tig + 4];
            #pragma unroll
            for (int nt = 0; nt < 8; nt++) {
                const unsigned b0 = Wbuf[(nt * 8 + gid) * WBUF_STRIDE + 8 * ks + tig];
                const unsigned b1 = Wbuf[(nt * 8 + gid) * WBUF_STRIDE + 8 * ks + tig + 4];
                mma_f16(acc[nt], a0, a1, a2, a3, b0, b1);
            }
        }

        if (z == 0) {
            // V: bias + ReLU -> Vsp plain layout
            #pragma unroll
            for (int nt = 0; nt < 8; nt++) {
                float2 bias = *(const float2*)(bb + n0 + nt * 8 + 2 * tig);
                float c0 = fmaxf(acc[nt][0] + bias.x, 0.f);
                float c1 = fmaxf(acc[nt][1] + bias.y, 0.f);
                float c2 = fmaxf(acc[nt][2] + bias.x, 0.f);
                float c3 = fmaxf(acc[nt][3] + bias.y, 0.f);
                Vsp[row0 * VSP_STRIDE + nt * 4 + tig] = packh2(__floats2half2_rn(c0, c1));
                Vsp[row1 * VSP_STRIDE + nt * 4 + tig] = packh2(__floats2half2_rn(c2, c3));
            }
        } else if (z == 1) {
            // K: bias -> KTh direct (C-frag word == score B-operand word)
            #pragma unroll
            for (int nt = 0; nt < 8; nt++) {
                float2 bias = *(const float2*)(bb + n0 + nt * 8 + 2 * tig);
                float c0 = acc[nt][0] + bias.x;
                float c1 = acc[nt][1] + bias.y;
                float c2 = acc[nt][2] + bias.x;
                float c3 = acc[nt][3] + bias.y;
                const int base = ((nt >> 1) * 4 + tig) * (KTHS * 2) + (nt & 1);
                KThw[base + row0 * 2] = packh2(__floats2half2_rn(c0, c1));
                KThw[base + row1 * 2] = packh2(__floats2half2_rn(c2, c3));
            }
        } else {
            // Q: bias, xQSCALE (log2e folded), pack to score A-fragments
            #pragma unroll
            for (int nt = 0; nt < 8; nt++) {
                float2 bias = *(const float2*)(bb + n0 + nt * 8 + 2 * tig);
                acc[nt][0] = (acc[nt][0] + bias.x) * QSCALE;
                acc[nt][1] = (acc[nt][1] + bias.y) * QSCALE;
                acc[nt][2] = (acc[nt][2] + bias.x) * QSCALE;
                acc[nt][3] = (acc[nt][3] + bias.y) * QSCALE;
            }
            #pragma unroll
            for (int ks = 0; ks < 4; ks++) {
                qa[ks][0] = packh2(__floats2half2_rn(acc[2*ks  ][0], acc[2*ks  ][1]));
                qa[ks][1] = packh2(__floats2half2_rn(acc[2*ks  ][2], acc[2*ks  ][3]));
                qa[ks][2] = packh2(__floats2half2_rn(acc[2*ks+1][0], acc[2*ks+1][1]));
                qa[ks][3] = packh2(__floats2half2_rn(acc[2*ks+1][2], acc[2*ks+1][3]));
            }
        }

        // commit prefetched W after all reads of Wbuf for this pass are done
        if (z < 2) {
            __syncthreads();   // all warps done reading Wbuf
            #pragma unroll
            for (int j = 0; j < 3; j++) {
                const int i = tid + j * 352;
                if (i < 1024) {
                    const int n = i >> 4, c = (i & 15) * 4;
                    *(uint4*)(Wbuf + n * WBUF_STRIDE + c) = wpre[j];
                }
            }
            __syncthreads();   // Wbuf ready for next pass
        }
    }
    __syncthreads();   // K/V stores visible; xs dead

    // ---- repack Vsp -> Vp2 (PV B-operand: 4-key packs per dim) ----
    for (int i = tid; i < 44 * HD; i += 352) {
        const int r = i >> 6, d = i & 63;          // r = c*4 + tg
        const int c = r >> 2, tg = r & 3;
        const int k0 = 16 * c + 2 * tg;            // keys k0,k0+1,k0+8,k0+9
        const int dh = d >> 1, sel = d & 1;
        __half v0 = geth(Vsp[(k0    ) * VSP_STRIDE + dh], sel);
        __half v1 = geth(Vsp[(k0 + 1) * VSP_STRIDE + dh], sel);
        __half v2 = geth(Vsp[(k0 + 8) * VSP_STRIDE + dh], sel);
        __half v3 = geth(Vsp[(k0 + 9) * VSP_STRIDE + dh], sel);
        uint2 pk;
        pk.x = packh2(__halves2half2(v0, v1));
        pk.y = packh2(__halves2half2(v2, v3));
        Vp2[r * VP2S + d] = pk;
    }
    __syncthreads();

    // ---- Phase 2: attention ----
    float o[8][4];
    #pragma unroll
    for (int nt = 0; nt < 8; nt++)
        #pragma unroll
        for (int i = 0; i < 4; i++) o[nt][i] = 0.f;

    float sum0 = 0.f, sum1 = 0.f;

    #pragma unroll
    for (int c = 0; c < 11; c++) {
        float s0[4] = {0.f, 0.f, 0.f, 0.f};
        float s1[4] = {0.f, 0.f, 0.f, 0.f};
        #pragma unroll
        for (int ks = 0; ks < 4; ks++) {
            const uint2* kr = KTh + (ks * 4 + tig) * KTHS + 16 * c + gid;
            uint2 kb0 = kr[0];
            uint2 kb1 = kr[8];
            mma_f16(s0, qa[ks][0], qa[ks][1], qa[ks][2], qa[ks][3], kb0.x, kb0.y);
            mma_f16(s1, qa[ks][0], qa[ks][1], qa[ks][2], qa[ks][3], kb1.x, kb1.y);
        }

        const int ca = 16 * c + 2 * tig;
        const int cb = ca + 1, cc = ca + 8, cd = ca + 9;

        #define MSK(col, row, lo, v) \
            ((((unsigned)((col) - (lo)) < 22u) && ((col) != (row))) ? NEGV : (v))
        float e00 = ex2f(MSK(ca, row0, lo0, s0[0]));
        float e01 = ex2f(MSK(cb, row0, lo0, s0[1]));
        float e02 = ex2f(MSK(ca, row1, lo1, s0[2]));
        float e03 = ex2f(MSK(cb, row1, lo1, s0[3]));
        float e10 = ex2f(MSK(cc, row0, lo0, s1[0]));
        float e11 = ex2f(MSK(cd, row0, lo0, s1[1]));
        float e12 = ex2f(MSK(cc, row1, lo1, s1[2]));
        float e13 = ex2f(MSK(cd, row1, lo1, s1[3]));
        #undef MSK

        sum0 += (e00 + e01) + (e10 + e11);
        sum1 += (e02 + e03) + (e12 + e13);

        unsigned a0 = packh2(__floats2half2_rn(e00, e01));
        unsigned a1 = packh2(__floats2half2_rn(e02, e03));
        unsigned a2 = packh2(__floats2half2_rn(e10, e11));
        unsigned a3 = packh2(__floats2half2_rn(e12, e13));

        const uint2* vrow = Vp2 + (c * 4 + tig) * VP2S + gid;
        #pragma unroll
        for (int nt = 0; nt < 8; nt++) {
            uint2 bf = vrow[nt * 8];
            mma_f16(o[nt], a0, a1, a2, a3, bf.x, bf.y);
        }
    }

    sum0 += __shfl_xor_sync(0xffffffffu, sum0, 1);
    sum0 += __shfl_xor_sync(0xffffffffu, sum0, 2);
    sum1 += __shfl_xor_sync(0xffffffffu, sum1, 1);
    sum1 += __shfl_xor_sync(0xffffffffu, sum1, 2);
    const float inv0 = 1.0f / sum0;
    const float inv1 = 1.0f / sum1;

    const size_t obase = (size_t)b * SEQ * DMODEL + (size_t)h * HD;
    #pragma unroll
    for (int nt = 0; nt < 8; nt++) {
        const int d = nt * 8 + 2 * tig;
        float2 r0v; r0v.x = o[nt][0] * inv0; r0v.y = o[nt][1] * inv0;
        float2 r1v; r1v.x = o[nt][2] * inv1; r1v.y = o[nt][3] * inv1;
        *(float2*)(out + obase + (size_t)row0 * DMODEL + d) = r0v;
        *(float2*)(out + obase + (size_t)row1 * DMODEL + d) = r1v;
    }
}

// ---------------------------------------------------------------------------
extern "C" void kernel_launch(void* const* d_in, const int* in_sizes, int n_in,
                              void* d_out, int out_size)
{
    const float* x  = (const float*)d_in[0];
    const float* Wq = (const float*)d_in[1];
    const float* bq = (const float*)d_in[2];
    const float* Wk = (const float*)d_in[3];
    const float* bk = (const float*)d_in[4];
    const float* Wv = (const float*)d_in[5];
    const float* bv = (const float*)d_in[6];
    float* out = (float*)d_out;

    cudaFuncSetAttribute(fused_attn_kernel,
                         cudaFuncAttributeMaxDynamicSharedMemorySize, SMEM_TOTAL);

    prep_kernel<<<(PREP_THREADS + 255) / 256, 256>>>(x, Wq, Wk, Wv);
    fused_attn_kernel<<<BATCH * NH, 352, SMEM_TOTAL>>>(bq, bk, bv, out);
}

// round 17
// speedup vs baseline: 1.0762x; 1.0762x over previous
#include <cuda_runtime.h>
#include <cuda_fp16.h>

#define BATCH   512
#define SEQ     176
#define DIN     128
#define NH      8
#define HD      64
#define DMODEL  512
#define NEGV    (-9e15f)
#define M_TOTAL (BATCH * SEQ)          // 90112
#define QSCALE  0.1803368787f           // 0.125 * log2(e)

// ---------------- smem layout (bytes) — identical to R15 ----------------
#define WBUF_STRIDE 68
#define WBUF_BYTES  (64 * WBUF_STRIDE * 4)        // 17408
#define KTHS        180
#define KTH_BYTES   (16 * KTHS * 8)               // 23040
#define VSP_STRIDE  33
#define VSP_BYTES   (SEQ * VSP_STRIDE * 4)        // 23232
#define XS_STRIDE   68
#define XS_BYTES    (SEQ * XS_STRIDE * 4)         // 47872
#define VP2S        76
#define VP2_BYTES   (44 * VP2S * 8)               // 26752 (overlays xs)

#define OFF_WBUF 0
#define OFF_KTH  (OFF_WBUF + WBUF_BYTES)
#define OFF_VSP  (OFF_KTH + KTH_BYTES)
#define OFF_XS   (OFF_VSP + VSP_BYTES)            // 63680 (16B aligned)
#define OFF_VP2  OFF_XS
#define SMEM_TOTAL (OFF_XS + XS_BYTES)            // 111552

// pre-converted fp16 operands (packed half2 k-pair words, smem word order)
static __device__ unsigned g_x16[(size_t)M_TOTAL * 64];      // [m][p]
static __device__ unsigned g_W16[3 * DMODEL * 64];           // [z][n][p]

#define XPART (M_TOTAL * 32)            // vectorized x threads (2 words each)
#define WPART (3 * DMODEL * 64)         // w threads (1 word each)
#define PREP_THREADS (XPART + WPART)

__device__ __forceinline__ unsigned packh2(__half2 h) {
    return *reinterpret_cast<unsigned*>(&h);
}
__device__ __forceinline__ __half geth(unsigned w, int sel) {
    __half2 h = *reinterpret_cast<__half2*>(&w);
    return sel ? __high2half(h) : __low2half(h);
}
__device__ __forceinline__ float ex2f(float x) {
    float r; asm("ex2.approx.f32 %0, %1;" : "=f"(r) : "f"(x)); return r;
}

__device__ __forceinline__ void mma_f16(float c[4],
                                        unsigned a0, unsigned a1, unsigned a2, unsigned a3,
                                        unsigned b0, unsigned b1) {
    asm volatile(
        "mma.sync.aligned.m16n8k16.row.col.f32.f16.f16.f32 "
        "{%0,%1,%2,%3}, {%4,%5,%6,%7}, {%8,%9}, {%0,%1,%2,%3};"
        : "+f"(c[0]), "+f"(c[1]), "+f"(c[2]), "+f"(c[3])
        : "r"(a0), "r"(a1), "r"(a2), "r"(a3), "r"(b0), "r"(b1));
}

// ---------------------------------------------------------------------------
// Merged prep kernel: x part vectorized (float4 -> uint2), W part scalar.
// ---------------------------------------------------------------------------
__global__ void prep_kernel(const float* __restrict__ x,
                            const float* __restrict__ Wq,
                            const float* __restrict__ Wk,
                            const float* __restrict__ Wv)
{
    const int idx = blockIdx.x * 256 + threadIdx.x;
    if (idx < XPART) {
        const int m = idx >> 5, p2 = idx & 31;       // p2 = pair-of-words index
        float4 v = *(const float4*)(x + (size_t)m * DIN + 4 * p2);
        uint2 o;
        o.x = packh2(__floats2half2_rn(v.x, v.y));
        o.y = packh2(__floats2half2_rn(v.z, v.w));
        *(uint2*)(g_x16 + (size_t)m * 64 + 2 * p2) = o;
    } else if (idx < PREP_THREADS) {
        const int r = idx - XPART;                    // [z][n][p] flat, 3*512*64
        const int z = r >> 15;
        const int rr = r & 32767;
        const int p = rr >> 9, n = rr & 511;
        const float* W = (z == 0) ? Wq : (z == 1) ? Wk : Wv;
        const float w0 = W[(size_t)(2 * p    ) * DMODEL + n];
        const float w1 = W[(size_t)(2 * p + 1) * DMODEL + n];
        g_W16[z * (DMODEL * 64) + n * 64 + p] = packh2(__floats2half2_rn(w0, w1));
    }
}

// ---------------------------------------------------------------------------
// Fused kernel — byte-identical to R15 (289us best).
// One block per (b,h). 352 threads (11 warps), 2 CTAs/SM.
// ---------------------------------------------------------------------------
__global__ void __launch_bounds__(352, 2)
fused_attn_kernel(const float* __restrict__ bq,
                  const float* __restrict__ bk,
                  const float* __restrict__ bv,
                  float* __restrict__ out)
{
    extern __shared__ char sm[];
    unsigned* Wbuf = (unsigned*)(sm + OFF_WBUF);   // [64 n][68]
    uint2*    KTh  = (uint2*)(sm + OFF_KTH);       // [16][180]
    unsigned* KThw = (unsigned*)(sm + OFF_KTH);
    unsigned* Vsp  = (unsigned*)(sm + OFF_VSP);    // [176][33]
    unsigned* xs   = (unsigned*)(sm + OFF_XS);     // [176][68]
    uint2*    Vp2  = (uint2*)(sm + OFF_VP2);       // [44][76]

    const int tid = threadIdx.x;
    const int bh  = blockIdx.x;
    const int b   = bh >> 3;
    const int h   = bh & 7;
    const int n0  = h * HD;

    // ---- stage x[b]: pure uint4 copy ----
    const unsigned* xg = g_x16 + (size_t)b * SEQ * 64;
    for (int i = tid; i < SEQ * 16; i += 352) {
        const int r = i >> 4, c = (i & 15) * 4;
        *(uint4*)(xs + r * XS_STRIDE + c) = *(const uint4*)(xg + r * 64 + c);
    }

    const int w    = tid >> 5;
    const int lane = tid & 31;
    const int gid  = lane >> 2;
    const int tig  = lane & 3;
    const int row0 = w * 16 + gid;
    const int row1 = row0 + 8;
    const int lo0  = (row0 / 22) * 22;
    const int lo1  = (row1 / 22) * 22;

    unsigned qa[4][4];   // Q score A-fragments (filled by z==2 pass)

    // ---- Phase 1: three projection passes (V, K, Q) ----
    #pragma unroll 1
    for (int z = 0; z < 3; z++) {
        const int wz = (z == 0) ? 2 : (z == 1) ? 1 : 0;   // g_W16 index (0=q,1=k,2=v)
        const float* bb = (z == 0) ? bv : (z == 1) ? bk : bq;

        __syncthreads();   // Wbuf reuse / xs ready on first iter
        {
            const unsigned* wg = g_W16 + wz * (DMODEL * 64) + (size_t)n0 * 64;
            for (int i = tid; i < 64 * 16; i += 352) {
                const int n = i >> 4, c = (i & 15) * 4;
                *(uint4*)(Wbuf + n * WBUF_STRIDE + c) = *(const uint4*)(wg + n * 64 + c);
            }
        }
        __syncthreads();

        float acc[8][4];
        #pragma unroll
        for (int nt = 0; nt < 8; nt++)
            #pragma unroll
            for (int i = 0; i < 4; i++) acc[nt][i] = 0.f;

        #pragma unroll
        for (int ks = 0; ks < 8; ks++) {
            const unsigned a0 = xs[row0 * XS_STRIDE + 8 * ks + tig];
            const unsigned a1 = xs[row1 * XS_STRIDE + 8 * ks + tig];
            const unsigned a2 = xs[row0 * XS_STRIDE + 8 * ks + tig + 4];
            const unsigned a3 = xs[row1 * XS_STRIDE + 8 * ks + tig + 4];
            #pragma unroll
            for (int nt = 0; nt < 8; nt++) {
                const unsigned b0 = Wbuf[(nt * 8 + gid) * WBUF_STRIDE + 8 * ks + tig];
                const unsigned b1 = Wbuf[(nt * 8 + gid) * WBUF_STRIDE + 8 * ks + tig + 4];
                mma_f16(acc[nt], a0, a1, a2, a3, b0, b1);
            }
        }

        if (z == 0) {
            // V: bias + ReLU -> Vsp plain layout
            #pragma unroll
            for (int nt = 0; nt < 8; nt++) {
                float2 bias = *(const float2*)(bb + n0 + nt * 8 + 2 * tig);
                float c0 = fmaxf(acc[nt][0] + bias.x, 0.f);
                float c1 = fmaxf(acc[nt][1] + bias.y, 0.f);
                float c2 = fmaxf(acc[nt][2] + bias.x, 0.f);
                float c3 = fmaxf(acc[nt][3] + bias.y, 0.f);
                Vsp[row0 * VSP_STRIDE + nt * 4 + tig] = packh2(__floats2half2_rn(c0, c1));
                Vsp[row1 * VSP_STRIDE + nt * 4 + tig] = packh2(__floats2half2_rn(c2, c3));
            }
        } else if (z == 1) {
            // K: bias -> KTh direct (C-frag word == score B-operand word)
            #pragma unroll
            for (int nt = 0; nt < 8; nt++) {
                float2 bias = *(const float2*)(bb + n0 + nt * 8 + 2 * tig);
                float c0 = acc[nt][0] + bias.x;
                float c1 = acc[nt][1] + bias.y;
                float c2 = acc[nt][2] + bias.x;
                float c3 = acc[nt][3] + bias.y;
                const int base = ((nt >> 1) * 4 + tig) * (KTHS * 2) + (nt & 1);
                KThw[base + row0 * 2] = packh2(__floats2half2_rn(c0, c1));
                KThw[base + row1 * 2] = packh2(__floats2half2_rn(c2, c3));
            }
        } else {
            // Q: bias, xQSCALE (log2e folded), pack to score A-fragments
            #pragma unroll
            for (int nt = 0; nt < 8; nt++) {
                float2 bias = *(const float2*)(bb + n0 + nt * 8 + 2 * tig);
                acc[nt][0] = (acc[nt][0] + bias.x) * QSCALE;
                acc[nt][1] = (acc[nt][1] + bias.y) * QSCALE;
                acc[nt][2] = (acc[nt][2] + bias.x) * QSCALE;
                acc[nt][3] = (acc[nt][3] + bias.y) * QSCALE;
            }
            #pragma unroll
            for (int ks = 0; ks < 4; ks++) {
                qa[ks][0] = packh2(__floats2half2_rn(acc[2*ks  ][0], acc[2*ks  ][1]));
                qa[ks][1] = packh2(__floats2half2_rn(acc[2*ks  ][2], acc[2*ks  ][3]));
                qa[ks][2] = packh2(__floats2half2_rn(acc[2*ks+1][0], acc[2*ks+1][1]));
                qa[ks][3] = packh2(__floats2half2_rn(acc[2*ks+1][2], acc[2*ks+1][3]));
            }
        }
    }
    __syncthreads();   // K/V stores visible; xs dead

    // ---- repack Vsp -> Vp2 (PV B-operand: 4-key packs per dim) ----
    for (int i = tid; i < 44 * HD; i += 352) {
        const int r = i >> 6, d = i & 63;          // r = c*4 + tg
        const int c = r >> 2, tg = r & 3;
        const int k0 = 16 * c + 2 * tg;            // keys k0,k0+1,k0+8,k0+9
        const int dh = d >> 1, sel = d & 1;
        __half v0 = geth(Vsp[(k0    ) * VSP_STRIDE + dh], sel);
        __half v1 = geth(Vsp[(k0 + 1) * VSP_STRIDE + dh], sel);
        __half v2 = geth(Vsp[(k0 + 8) * VSP_STRIDE + dh], sel);
        __half v3 = geth(Vsp[(k0 + 9) * VSP_STRIDE + dh], sel);
        uint2 pk;
        pk.x = packh2(__halves2half2(v0, v1));
        pk.y = packh2(__halves2half2(v2, v3));
        Vp2[r * VP2S + d] = pk;
    }
    __syncthreads();

    // ---- Phase 2: attention ----
    float o[8][4];
    #pragma unroll
    for (int nt = 0; nt < 8; nt++)
        #pragma unroll
        for (int i = 0; i < 4; i++) o[nt][i] = 0.f;

    float sum0 = 0.f, sum1 = 0.f;

    #pragma unroll
    for (int c = 0; c < 11; c++) {
        float s0[4] = {0.f, 0.f, 0.f, 0.f};
        float s1[4] = {0.f, 0.f, 0.f, 0.f};
        #pragma unroll
        for (int ks = 0; ks < 4; ks++) {
            const uint2* kr = KTh + (ks * 4 + tig) * KTHS + 16 * c + gid;
            uint2 kb0 = kr[0];
            uint2 kb1 = kr[8];
            mma_f16(s0, qa[ks][0], qa[ks][1], qa[ks][2], qa[ks][3], kb0.x, kb0.y);
            mma_f16(s1, qa[ks][0], qa[ks][1], qa[ks][2], qa[ks][3], kb1.x, kb1.y);
        }

        const int ca = 16 * c + 2 * tig;
        const int cb = ca + 1, cc = ca + 8, cd = ca + 9;

        #define MSK(col, row, lo, v) \
            ((((unsigned)((col) - (lo)) < 22u) && ((col) != (row))) ? NEGV : (v))
        float e00 = ex2f(MSK(ca, row0, lo0, s0[0]));
        float e01 = ex2f(MSK(cb, row0, lo0, s0[1]));
        float e02 = ex2f(MSK(ca, row1, lo1, s0[2]));
        float e03 = ex2f(MSK(cb, row1, lo1, s0[3]));
        float e10 = ex2f(MSK(cc, row0, lo0, s1[0]));
        float e11 = ex2f(MSK(cd, row0, lo0, s1[1]));
        float e12 = ex2f(MSK(cc, row1, lo1, s1[2]));
        float e13 = ex2f(MSK(cd, row1, lo1, s1[3]));
        #undef MSK

        sum0 += (e00 + e01) + (e10 + e11);
        sum1 += (e02 + e03) + (e12 + e13);

        unsigned a0 = packh2(__floats2half2_rn(e00, e01));
        unsigned a1 = packh2(__floats2half2_rn(e02, e03));
        unsigned a2 = packh2(__floats2half2_rn(e10, e11));
        unsigned a3 = packh2(__floats2half2_rn(e12, e13));

        const uint2* vrow = Vp2 + (c * 4 + tig) * VP2S + gid;
        #pragma unroll
        for (int nt = 0; nt < 8; nt++) {
            uint2 bf = vrow[nt * 8];
            mma_f16(o[nt], a0, a1, a2, a3, bf.x, bf.y);
        }
    }

    sum0 += __shfl_xor_sync(0xffffffffu, sum0, 1);
    sum0 += __shfl_xor_sync(0xffffffffu, sum0, 2);
    sum1 += __shfl_xor_sync(0xffffffffu, sum1, 1);
    sum1 += __shfl_xor_sync(0xffffffffu, sum1, 2);
    const float inv0 = 1.0f / sum0;
    const float inv1 = 1.0f / sum1;

    const size_t obase = (size_t)b * SEQ * DMODEL + (size_t)h * HD;
    #pragma unroll
    for (int nt = 0; nt < 8; nt++) {
        const int d = nt * 8 + 2 * tig;
        float2 r0v; r0v.x = o[nt][0] * inv0; r0v.y = o[nt][1] * inv0;
        float2 r1v; r1v.x = o[nt][2] * inv1; r1v.y = o[nt][3] * inv1;
        *(float2*)(out + obase + (size_t)row0 * DMODEL + d) = r0v;
        *(float2*)(out + obase + (size_t)row1 * DMODEL + d) = r1v;
    }
}

// ---------------------------------------------------------------------------
extern "C" void kernel_launch(void* const* d_in, const int* in_sizes, int n_in,
                              void* d_out, int out_size)
{
    const float* x  = (const float*)d_in[0];
    const float* Wq = (const float*)d_in[1];
    const float* bq = (const float*)d_in[2];
    const float* Wk = (const float*)d_in[3];
    const float* bk = (const float*)d_in[4];
    const float* Wv = (const float*)d_in[5];
    const float* bv = (const float*)d_in[6];
    float* out = (float*)d_out;

    cudaFuncSetAttribute(fused_attn_kernel,
                         cudaFuncAttributeMaxDynamicSharedMemorySize, SMEM_TOTAL);

    prep_kernel<<<(PREP_THREADS + 255) / 256, 256>>>(x, Wq, Wk, Wv);
    fused_attn_kernel<<<BATCH * NH, 352, SMEM_TOTAL>>>(bq, bk, bv, out);
}